// round 15
// baseline (speedup 1.0000x reference)
#include <cuda_runtime.h>
#include <math.h>

// PyTorchCG: BS=64, N=1024, maxiter derived from out_size.
#define CG_N  1024
#define CG_BS 64
#define TS    128
#define NT    8                    // CG_N / TS
#define NPAIR 36                   // NT*(NT+1)/2
#define TILE_F  (TS * TS)
#define TILE_F4 (TILE_F / 4)

// Persistent state (no allocs -> __device__ globals; zero-initialized).
__device__ float g_r2 [2][CG_BS * CG_N];
__device__ float g_p2 [2][CG_BS * CG_N];
__device__ float g_Ap3[3][CG_BS * CG_N];   // consume / accumulate / zero rotation
__device__ float g_d  [CG_BS * CG_N];      // diag(M_inv)
__device__ float g_rz2[2][CG_BS];
__device__ float g_pap3[3][CG_BS];
// Packed upper-triangle tiles: [b][pair][128x128] contiguous (144 MB scratch).
__device__ __align__(16) float g_pack[(size_t)CG_BS * NPAIR * TILE_F];

// ---------------------------------------------------------------------------
// Pack upper-triangle tiles of A contiguously + extract diag(M_inv).
// grid=(N/8,BS), block=256.
// ---------------------------------------------------------------------------
__global__ void __launch_bounds__(256) k_pack(const float* __restrict__ A,
                                              const float* __restrict__ Minv)
{
    const int b    = blockIdx.y;
    const int warp = threadIdx.x >> 5;
    const int lane = threadIdx.x & 31;
    const int row  = (blockIdx.x << 3) + warp;
    const int bi   = row >> 7;
    const int rloc = row & (TS - 1);

    const float4* Arow =
        reinterpret_cast<const float4*>(A + ((size_t)b * CG_N + row) * CG_N);

    for (int k = bi; k < NT; ++k) {
        float4 a = Arow[lane + 32 * k];
        const int li = bi * NT - (bi * (bi - 1)) / 2 + (k - bi);
        reinterpret_cast<float4*>(g_pack)
            [((size_t)b * NPAIR + li) * TILE_F4 + rloc * 32 + lane] = a;
    }
    if (lane == 0)
        g_d[(size_t)b * CG_N + row] =
            Minv[(size_t)b * CG_N * CG_N + (size_t)row * CG_N + row];
}

// ---------------------------------------------------------------------------
// Deterministic block sum of two values over 256 threads.
// ---------------------------------------------------------------------------
__device__ __forceinline__ void block_sum2(float* sbuf, float a, float b,
                                           float& ra, float& rb)
{
    const int tid = threadIdx.x;
#pragma unroll
    for (int off = 16; off; off >>= 1) {
        a += __shfl_xor_sync(0xffffffffu, a, off);
        b += __shfl_xor_sync(0xffffffffu, b, off);
    }
    if ((tid & 31) == 0) { sbuf[tid >> 5] = a; sbuf[8 + (tid >> 5)] = b; }
    __syncthreads();
    if (tid < 8) {
        float wa = sbuf[tid], wb = sbuf[8 + tid];
#pragma unroll
        for (int off = 4; off; off >>= 1) {
            wa += __shfl_xor_sync(0x000000ffu, wa, off);
            wb += __shfl_xor_sync(0x000000ffu, wb, off);
        }
        if (tid == 0) { sbuf[0] = wa; sbuf[8] = wb; }
    }
    __syncthreads();
    ra = sbuf[0];
    rb = sbuf[8];
    __syncthreads();
}

// ---------------------------------------------------------------------------
// Shared state.
// ---------------------------------------------------------------------------
struct SMem {
    float sd[8][16][33];
    float scol[8][TS];
    float sbuf[16];
    __align__(16) float pnew[CG_N];   // p vector for this batch (smem-resident)
};

// ---------------------------------------------------------------------------
// R4 symmetric tile body.  spi/spj point into smem pnew.
// Accumulates Ap_dst (atomics) and *pap_dst.
// ---------------------------------------------------------------------------
__device__ __forceinline__ void tile_mv(SMem& sm, const float4* T,
                                        const float* spi, const float* spj,
                                        int bi, int bj, bool diag,
                                        float* Ap_dst, float* pap_dst)
{
    const int tid  = threadIdx.x;
    const int warp = tid >> 5;
    const int lane = tid & 31;

    const float4 pj4 = reinterpret_cast<const float4*>(spj)[lane];
    float4 cacc = make_float4(0.f, 0.f, 0.f, 0.f);

    {
        float4 a[8];
#pragma unroll
        for (int k = 0; k < 8; ++k) a[k] = T[k * 32 + lane];
#pragma unroll
        for (int k = 0; k < 8; ++k) {
            sm.sd[warp][k][lane] = a[k].x * pj4.x + a[k].y * pj4.y +
                                   a[k].z * pj4.z + a[k].w * pj4.w;
            const float pir = spi[16 * warp + k];
            cacc.x += a[k].x * pir;  cacc.y += a[k].y * pir;
            cacc.z += a[k].z * pir;  cacc.w += a[k].w * pir;
        }
    }
    {
        float4 a[8];
#pragma unroll
        for (int k = 0; k < 8; ++k) a[k] = T[(k + 8) * 32 + lane];
#pragma unroll
        for (int k = 0; k < 8; ++k) {
            sm.sd[warp][k + 8][lane] = a[k].x * pj4.x + a[k].y * pj4.y +
                                       a[k].z * pj4.z + a[k].w * pj4.w;
            const float pir = spi[16 * warp + 8 + k];
            cacc.x += a[k].x * pir;  cacc.y += a[k].y * pir;
            cacc.z += a[k].z * pir;  cacc.w += a[k].w * pir;
        }
    }

    if (!diag) {
        sm.scol[warp][4 * lane + 0] = cacc.x;
        sm.scol[warp][4 * lane + 1] = cacc.y;
        sm.scol[warp][4 * lane + 2] = cacc.z;
        sm.scol[warp][4 * lane + 3] = cacc.w;
    }
    __syncthreads();

    // row dots -> y_bi
    const int ri = tid >> 1;
    const int hi = tid & 1;
    float s = 0.f;
#pragma unroll
    for (int j = 0; j < 16; ++j)
        s += sm.sd[ri >> 4][ri & 15][16 * hi + j];
    s += __shfl_xor_sync(0xffffffffu, s, 1);

    float pap_c = 0.f;
    if (hi == 0) {
        atomicAdd(&Ap_dst[bi * TS + ri], s);
        pap_c = s * spi[ri];
    }

    // transpose part -> y_bj
    if (!diag && tid < TS) {
        float cs = 0.f;
#pragma unroll
        for (int w = 0; w < 8; ++w) cs += sm.scol[w][tid];
        atomicAdd(&Ap_dst[bj * TS + tid], cs);
    }

    if (pap_dst) {
#pragma unroll
        for (int off = 16; off; off >>= 1)
            pap_c += __shfl_xor_sync(0xffffffffu, pap_c, off);
        if (lane == 0) sm.sbuf[warp] = pap_c;
        __syncthreads();
        if (tid == 0) {
            float t = 0.f;
#pragma unroll
            for (int w = 0; w < 8; ++w) t += sm.sbuf[w];
            atomicAdd(pap_dst, diag ? t : 2.f * t);
        }
    }
}

// ---------------------------------------------------------------------------
// mv(x0): symmetric matvec of x0 into g_Ap3[2].  grid=(NPAIR, BS).
// ---------------------------------------------------------------------------
__global__ void __launch_bounds__(256) k_mvx0(const float* __restrict__ x0)
{
    __shared__ SMem sm;
    const int b   = blockIdx.y;
    const int tid = threadIdx.x;

    int li = blockIdx.x, bi = 0;
    while (li >= NT - bi) { li -= NT - bi; ++bi; }
    const int  bj   = bi + li;
    const bool diag = (bi == bj);

    reinterpret_cast<float4*>(sm.pnew)[tid] =
        reinterpret_cast<const float4*>(x0 + (size_t)b * CG_N)[tid];
    __syncthreads();

    const float4* T = reinterpret_cast<const float4*>(g_pack) +
                      ((size_t)b * NPAIR + blockIdx.x) * TILE_F4 +
                      (size_t)(tid >> 5) * 16 * 32;

    tile_mv(sm, T, sm.pnew + bi * TS, sm.pnew + bj * TS,
            bi, bj, diag, g_Ap3[2] + (size_t)b * CG_N, nullptr);
}

// ---------------------------------------------------------------------------
// Fused iteration kernel K_i, grid=(NPAIR, BS), one launch per iteration.
//   consume cn=(i+2)%3, accum ac=i%3, zero zr=(i+1)%3.
// NEW: the CTA's whole 64KB tile is L2-prefetched FIRST (no regs/smem cost),
// so the DRAM stream runs concurrently with the serial update head.
// ---------------------------------------------------------------------------
__global__ void __launch_bounds__(256) k_iter(int i,
                                              const float* __restrict__ bvec,
                                              float* __restrict__ out,
                                              int ldout, int do_mv)
{
    __shared__ SMem sm;
    const int b   = blockIdx.y;
    const int tid = threadIdx.x;

    int li = blockIdx.x, bi = 0;
    while (li >= NT - bi) { li -= NT - bi; ++bi; }
    const int  bj   = bi + li;
    const bool diag = (bi == bj);

    const int cn = (i + 2) % 3;
    const int ac = i % 3;
    const int zr = (i + 1) % 3;

    // --- L2 prefetch of this CTA's packed tile (64KB = 512 x 128B lines) ---
    const char* Tc = reinterpret_cast<const char*>(g_pack) +
                     ((size_t)b * NPAIR + blockIdx.x) * (TILE_F * 4);
    if (do_mv) {
        asm volatile("prefetch.global.L2 [%0];" :: "l"(Tc + (size_t)tid * 128));
        asm volatile("prefetch.global.L2 [%0];" :: "l"(Tc + 32768 + (size_t)tid * 128));
    }

    // --- redundant update for batch b (float4, identical in every CTA) ---
    const float4* Apc4 = reinterpret_cast<const float4*>(g_Ap3[cn] + (size_t)b * CG_N);
    const float4* d4p  = reinterpret_cast<const float4*>(g_d + (size_t)b * CG_N);

    float4 rv4, z4, pn4;
    float rz_p, rr_p;

    const float4 ap = Apc4[tid];
    const float4 dd = d4p[tid];

    if (i == 0) {
        const float4 bb = reinterpret_cast<const float4*>(bvec + (size_t)b * CG_N)[tid];
        rv4.x = bb.x - ap.x;  rv4.y = bb.y - ap.y;
        rv4.z = bb.z - ap.z;  rv4.w = bb.w - ap.w;
    } else {
        const float alpha = g_rz2[(i - 1) & 1][b] / g_pap3[cn][b];
        const float4 ro = reinterpret_cast<const float4*>(g_r2[(i - 1) & 1] +
                                                          (size_t)b * CG_N)[tid];
        rv4.x = ro.x - alpha * ap.x;  rv4.y = ro.y - alpha * ap.y;
        rv4.z = ro.z - alpha * ap.z;  rv4.w = ro.w - alpha * ap.w;
    }
    z4.x = dd.x * rv4.x;  z4.y = dd.y * rv4.y;
    z4.z = dd.z * rv4.z;  z4.w = dd.w * rv4.w;
    rz_p = rv4.x * z4.x + rv4.y * z4.y + rv4.z * z4.z + rv4.w * z4.w;
    rr_p = rv4.x * rv4.x + rv4.y * rv4.y + rv4.z * rv4.z + rv4.w * rv4.w;

    float rz_new, rr;
    block_sum2(sm.sbuf, rz_p, rr_p, rz_new, rr);

    if (i == 0) {
        pn4 = z4;
    } else {
        const float beta = rz_new / g_rz2[(i - 1) & 1][b];
        const float4 po = reinterpret_cast<const float4*>(g_p2[(i - 1) & 1] +
                                                          (size_t)b * CG_N)[tid];
        pn4.x = z4.x + beta * po.x;  pn4.y = z4.y + beta * po.y;
        pn4.z = z4.z + beta * po.z;  pn4.w = z4.w + beta * po.w;
    }
    reinterpret_cast<float4*>(sm.pnew)[tid] = pn4;

    // persist state + output (designated CTA), zero rotation buffers
    if (blockIdx.x == 0) {
        reinterpret_cast<float4*>(g_r2[i & 1] + (size_t)b * CG_N)[tid] = rv4;
        reinterpret_cast<float4*>(g_p2[i & 1] + (size_t)b * CG_N)[tid] = pn4;
        if (tid == 0) {
            g_rz2[i & 1][b] = rz_new;
            g_pap3[zr][b]   = 0.f;
            out[(size_t)b * ldout + i] = sqrtf(rr);
        }
    }
    if (diag && tid < 32)                          // zero Ap3[zr] segment bi
        reinterpret_cast<float4*>(g_Ap3[zr] + (size_t)b * CG_N + bi * TS)[tid] =
            make_float4(0.f, 0.f, 0.f, 0.f);

    if (!do_mv) return;
    __syncthreads();                               // pnew ready

    // --- symmetric tile matvec from SMEM p_new (tile now L2-resident) ---
    const float4* T = reinterpret_cast<const float4*>(g_pack) +
                      ((size_t)b * NPAIR + blockIdx.x) * TILE_F4 +
                      (size_t)(tid >> 5) * 16 * 32;

    tile_mv(sm, T, sm.pnew + bi * TS, sm.pnew + bj * TS,
            bi, bj, diag,
            g_Ap3[ac] + (size_t)b * CG_N, &g_pap3[ac][b]);
}

// ---------------------------------------------------------------------------
// kernel_launch: 2 + (maxiter+1) graph-capturable launches, no device sync.
// ---------------------------------------------------------------------------
extern "C" void kernel_launch(void* const* d_in, const int* in_sizes, int n_in,
                              void* d_out, int out_size)
{
    const float* A    = (const float*)d_in[0];
    const float* bvec = (const float*)d_in[1];
    const float* x0   = (const float*)d_in[2];
    const float* Minv = (const float*)d_in[3];
    float* out        = (float*)d_out;

    const int ldout   = out_size / CG_BS;   // maxiter + 1
    const int maxiter = ldout - 1;

    dim3 grid_pk(CG_N / 8, CG_BS);
    dim3 grid_mv(NPAIR, CG_BS);

    k_pack<<<grid_pk, 256>>>(A, Minv);
    k_mvx0<<<grid_mv, 256>>>(x0);                       // A@x0 -> Ap3[2]

    for (int i = 0; i <= maxiter; ++i)
        k_iter<<<grid_mv, 256>>>(i, bvec, out, ldout, i < maxiter ? 1 : 0);
}